// round 1
// baseline (speedup 1.0000x reference)
#include <cuda_runtime.h>
#include <math.h>

#define T_NO   200
#define SUBN   20
#define E_NOC  2000
#define I_NOC  500
#define T_DATA 10000
#define COS_NO 17

// ---------------- device scratch (static allocation only) ----------------
__device__ float g_se[T_DATA * SUBN];     // aggregated excitatory input per subunit
__device__ float g_si[T_DATA * SUBN];     // aggregated inhibitory input per subunit
__device__ float g_syn[T_DATA * SUBN];    // filtered synaptic drive
__device__ float g_ek[SUBN * T_NO];
__device__ float g_ik[SUBN * T_NO];
__device__ float g_spkk[SUBN * T_NO];
__device__ float g_histk[SUBN * T_NO];
__device__ int   g_idx_e[E_NOC];
__device__ int   g_idx_i[I_NOC];

// ---------------- K0: derive one-hot indices, build all kernels, emit filters ----------------
__global__ void prep_kernel(const float* __restrict__ C_syn_e,
                            const float* __restrict__ C_syn_i,
                            const float* __restrict__ Tau_syn,
                            const float* __restrict__ Delta_syn,
                            const float* __restrict__ W_syn,
                            const float* __restrict__ Tau_spk,
                            const float* __restrict__ W_spk,
                            const float* __restrict__ W_hist,
                            float* __restrict__ filt_out)
{
    int tid = threadIdx.x;
    int nt  = blockDim.x;

    for (int e = tid; e < E_NOC; e += nt) {
        int k = 0;
        for (int s = 0; s < SUBN; s++)
            if (C_syn_e[s * E_NOC + e] > 0.5f) k = s;
        g_idx_e[e] = k;
    }
    for (int e = tid; e < I_NOC; e += nt) {
        int k = 0;
        for (int s = 0; s < SUBN; s++)
            if (C_syn_i[s * I_NOC + e] > 0.5f) k = s;
        g_idx_i[e] = k;
    }

    const float PIF = 3.14159265358979323846f;
    for (int i = tid; i < SUBN * T_NO; i += nt) {
        int s = i / T_NO;
        int m = i % T_NO;
        float mf = (float)m;

        // excitatory alpha kernel
        float te  = fmaxf(mf - expf(Delta_syn[s * 2 + 0]), 0.0f);
        float tte = te / expf(Tau_syn[s * 2 + 0]);
        float ek  = tte * expf(-tte) * expf(W_syn[s * 2 + 0]);

        // inhibitory alpha kernel (negative)
        float td  = fmaxf(mf - expf(Delta_syn[s * 2 + 1]), 0.0f);
        float tti = td / expf(Tau_syn[s * 2 + 1]);
        float ik  = -tti * expf(-tti) * expf(W_syn[s * 2 + 1]);

        // spike (alpha) kernel
        float tts = mf / expf(Tau_spk[s]);
        float sk  = tts * expf(-tts) * expf(W_spk[s]);

        // history kernel = W_hist @ raised-cosine log-time basis
        float raw = 4.0f * logf(mf + 1.0f);
        float hk  = 0.0f;
        for (int c = 0; c < COS_NO; c++) {
            float phi = (PIF * 0.5f) * (float)c;
            if (raw >= phi - PIF && raw <= phi + PIF)
                hk += W_hist[s * COS_NO + c] * (0.5f * cosf(raw - phi) + 0.5f);
        }

        g_ek[i]   = ek;
        g_ik[i]   = ik;
        g_spkk[i] = sk;
        g_histk[i]= hk;

        // filter output: rows 0-19 e_kern, 20-39 i_kern, 40-59 spk_kern, 60-79 hist_kern
        filt_out[(0 * SUBN + s) * T_NO + m] = ek;
        filt_out[(1 * SUBN + s) * T_NO + m] = ik;
        filt_out[(2 * SUBN + s) * T_NO + m] = sk;
        filt_out[(3 * SUBN + s) * T_NO + m] = hk;
    }
}

// ---------------- K1: one-hot scatter-sum of spikes into subunit bins ----------------
__global__ void agg_kernel(const float* __restrict__ S_e,
                           const float* __restrict__ S_i)
{
    __shared__ float acc_e[SUBN];
    __shared__ float acc_i[SUBN];
    int t   = blockIdx.x;
    int tid = threadIdx.x;
    if (tid < SUBN) { acc_e[tid] = 0.0f; acc_i[tid] = 0.0f; }
    __syncthreads();

    const float* re = S_e + (size_t)t * E_NOC;
    for (int e = tid; e < E_NOC; e += blockDim.x) {
        float v = re[e];
        if (v != 0.0f) atomicAdd(&acc_e[g_idx_e[e]], v);   // v is exactly 1.0 -> exact sums
    }
    const float* ri = S_i + (size_t)t * I_NOC;
    for (int e = tid; e < I_NOC; e += blockDim.x) {
        float v = ri[e];
        if (v != 0.0f) atomicAdd(&acc_i[g_idx_i[e]], v);
    }
    __syncthreads();
    if (tid < SUBN) {
        g_se[t * SUBN + tid] = acc_e[tid];
        g_si[t * SUBN + tid] = acc_i[tid];
    }
}

// ---------------- K2: causal FIR of syn drive with e/i kernels ----------------
// syn[t][s] = sum_{m=0}^{199} ek[s][m]*se[t-1-m][s] + ik[s][m]*si[t-1-m][s]
#define CONV_TS 128
__global__ void conv_kernel()
{
    __shared__ float ek[SUBN * T_NO];
    __shared__ float ik[SUBN * T_NO];
    int tid = threadIdx.x;
    for (int i = tid; i < SUBN * T_NO; i += blockDim.x) {
        ek[i] = g_ek[i];
        ik[i] = g_ik[i];
    }
    __syncthreads();

    int t0 = blockIdx.x * CONV_TS;
    for (int w = tid; w < CONV_TS * SUBN; w += blockDim.x) {
        int tt = t0 + w / SUBN;
        int s  = w % SUBN;
        if (tt >= T_DATA) continue;
        int mmax = min(T_NO, tt);   // indices t-1-m >= 0  <=>  m <= tt-1
        float acc = 0.0f;
        const float* eks = ek + s * T_NO;
        const float* iks = ik + s * T_NO;
        for (int m = 0; m < mmax; m++) {
            int ti = tt - 1 - m;
            acc = fmaf(eks[m], g_se[ti * SUBN + s], acc);
            acc = fmaf(iks[m], g_si[ti * SUBN + s], acc);
        }
        g_syn[tt * SUBN + s] = acc;
    }
}

// ---------------- K3: sequential recurrence, one persistent block ----------------
// 20 warps, warp w owns subunit w. Ring buffer of spikes (256 deep, pitch 21
// for bank-conflict freedom). Per step: 200-tap dot for hist & spk per warp,
// butterfly reduce, warp0 does C_den matvec + threshold + sigmoid.
#define RING_PITCH 21
#define RECUR_THREADS 640
// shared floats: histk 4000 + spkk 4000 + ring 256*21 + synb 256*21 + shh 32 + shq 32
#define RECUR_SMEM_FLOATS (4000 + 4000 + 256*RING_PITCH + 256*RING_PITCH + 32 + 32)

__global__ void __launch_bounds__(RECUR_THREADS, 1)
recur_kernel(const float* __restrict__ C_den,
             const float* __restrict__ Theta,
             float* __restrict__ Z,
             float* __restrict__ P)
{
    extern __shared__ float sm[];
    float* histk = sm;                        // 4000
    float* spkk  = histk + 4000;              // 4000
    float* ring  = spkk + 4000;               // 256*21
    float* synb  = ring + 256 * RING_PITCH;   // 256*21
    float* shh   = synb + 256 * RING_PITCH;   // 32
    float* shq   = shh + 32;                  // 32

    int tid  = threadIdx.x;
    int w    = tid >> 5;
    int lane = tid & 31;
    int s    = w;   // subunit owned by this warp (w in 0..19)

    for (int i = tid; i < SUBN * T_NO; i += RECUR_THREADS) {
        histk[i] = g_histk[i];
        spkk[i]  = g_spkk[i];
    }
    for (int i = tid; i < 256 * RING_PITCH; i += RECUR_THREADS) ring[i] = 0.0f;

    // warp0 lanes cache their C_den row + theta in registers
    float cd[SUBN];
    float th = 0.0f;
    if (w == 0 && lane < SUBN) {
        #pragma unroll
        for (int j = 0; j < SUBN; j++) cd[j] = C_den[lane * SUBN + j];
        th = Theta[lane];
    }
    __syncthreads();

    const float* hks = histk + s * T_NO;
    const float* qks = spkk  + s * T_NO;

    for (int t = 0; t < T_DATA; t++) {
        if ((t & 255) == 0) {
            // bulk-stage the next 256 rows of filtered syn drive
            for (int i = tid; i < 256 * SUBN; i += RECUR_THREADS) {
                int r = i / SUBN, c = i % SUBN;
                int tt = t + r;
                synb[r * RING_PITCH + c] = (tt < T_DATA) ? g_syn[tt * SUBN + c] : 0.0f;
            }
            __syncthreads();
        }

        float h = 0.0f, q = 0.0f;
        #pragma unroll
        for (int j = 0; j < 7; j++) {
            int m = lane + 32 * j;
            if (j < 6 || lane < 8) {   // m < 200
                int idx = (t - 1 - m) & 255;
                float zv = ring[idx * RING_PITCH + s];
                h = fmaf(hks[m], zv, h);
                q = fmaf(qks[m], zv, q);
            }
        }
        #pragma unroll
        for (int o = 16; o > 0; o >>= 1) {
            h += __shfl_xor_sync(0xFFFFFFFFu, h, o);
            q += __shfl_xor_sync(0xFFFFFFFFu, q, o);
        }
        if (lane == 0) { shh[s] = h; shq[s] = q; }
        __syncthreads();

        if (w == 0 && lane < SUBN) {
            float sv = synb[(t & 255) * RING_PITCH + lane] + th + shh[lane];
            #pragma unroll
            for (int j = 0; j < SUBN; j++) sv = fmaf(cd[j], shq[j], sv);
            float z = (sv > 0.0f) ? 1.0f : 0.0f;   // heaviside(x, 0)
            ring[(t & 255) * RING_PITCH + lane] = z;
            Z[t * SUBN + lane] = z;
            P[t * SUBN + lane] = 1.0f / (1.0f + expf(-sv));
        }
        __syncthreads();
    }
}

// ---------------- launch ----------------
extern "C" void kernel_launch(void* const* d_in, const int* in_sizes, int n_in,
                              void* d_out, int out_size)
{
    const float* S_e       = (const float*)d_in[0];
    const float* S_i       = (const float*)d_in[1];
    const float* C_den     = (const float*)d_in[2];
    const float* C_syn_e   = (const float*)d_in[3];
    const float* C_syn_i   = (const float*)d_in[4];
    const float* Tau_syn   = (const float*)d_in[5];
    const float* Delta_syn = (const float*)d_in[6];
    const float* W_syn     = (const float*)d_in[7];
    const float* Tau_spk   = (const float*)d_in[8];
    const float* W_spk     = (const float*)d_in[9];
    const float* W_hist    = (const float*)d_in[10];
    const float* Theta     = (const float*)d_in[11];

    float* out = (float*)d_out;
    float* Z = out;                          // [10000, 20]
    float* P = out + T_DATA * SUBN;          // [10000, 20]
    float* F = out + 2 * T_DATA * SUBN;      // [80, 200]

    prep_kernel<<<1, 256>>>(C_syn_e, C_syn_i, Tau_syn, Delta_syn, W_syn,
                            Tau_spk, W_spk, W_hist, F);
    agg_kernel<<<T_DATA, 256>>>(S_e, S_i);
    conv_kernel<<<(T_DATA + CONV_TS - 1) / CONV_TS, 256>>>();

    cudaFuncSetAttribute(recur_kernel,
                         cudaFuncAttributeMaxDynamicSharedMemorySize,
                         RECUR_SMEM_FLOATS * (int)sizeof(float));
    recur_kernel<<<1, RECUR_THREADS, RECUR_SMEM_FLOATS * sizeof(float)>>>(C_den, Theta, Z, P);
}

// round 2
// speedup vs baseline: 1.0001x; 1.0001x over previous
#include <cuda_runtime.h>
#include <math.h>

#define T_NO   200
#define SUBN   20
#define E_NOC  2000
#define I_NOC  500
#define T_DATA 10000
#define COS_NO 17

// ---------------- device scratch (static allocation only) ----------------
__device__ float g_se[T_DATA * SUBN];     // aggregated excitatory input per subunit
__device__ float g_si[T_DATA * SUBN];     // aggregated inhibitory input per subunit
__device__ float g_syn[T_DATA * SUBN];    // filtered synaptic drive
__device__ float g_ek[SUBN * T_NO];
__device__ float g_ik[SUBN * T_NO];
__device__ float g_spkk[SUBN * T_NO];
__device__ float g_histk[SUBN * T_NO];
__device__ int   g_idx_e[E_NOC];
__device__ int   g_idx_i[I_NOC];

// ---------------- K0: derive one-hot indices, build all kernels, emit filters ----------------
__global__ void prep_kernel(const float* __restrict__ C_syn_e,
                            const float* __restrict__ C_syn_i,
                            const float* __restrict__ Tau_syn,
                            const float* __restrict__ Delta_syn,
                            const float* __restrict__ W_syn,
                            const float* __restrict__ Tau_spk,
                            const float* __restrict__ W_spk,
                            const float* __restrict__ W_hist,
                            float* __restrict__ filt_out)
{
    int tid = threadIdx.x;
    int nt  = blockDim.x;

    for (int e = tid; e < E_NOC; e += nt) {
        int k = 0;
        for (int s = 0; s < SUBN; s++)
            if (C_syn_e[s * E_NOC + e] > 0.5f) k = s;
        g_idx_e[e] = k;
    }
    for (int e = tid; e < I_NOC; e += nt) {
        int k = 0;
        for (int s = 0; s < SUBN; s++)
            if (C_syn_i[s * I_NOC + e] > 0.5f) k = s;
        g_idx_i[e] = k;
    }

    const float PIF = 3.14159265358979323846f;
    for (int i = tid; i < SUBN * T_NO; i += nt) {
        int s = i / T_NO;
        int m = i % T_NO;
        float mf = (float)m;

        // excitatory alpha kernel
        float te  = fmaxf(mf - expf(Delta_syn[s * 2 + 0]), 0.0f);
        float tte = te / expf(Tau_syn[s * 2 + 0]);
        float ek  = tte * expf(-tte) * expf(W_syn[s * 2 + 0]);

        // inhibitory alpha kernel (negative)
        float td  = fmaxf(mf - expf(Delta_syn[s * 2 + 1]), 0.0f);
        float tti = td / expf(Tau_syn[s * 2 + 1]);
        float ik  = -tti * expf(-tti) * expf(W_syn[s * 2 + 1]);

        // spike (alpha) kernel
        float tts = mf / expf(Tau_spk[s]);
        float sk  = tts * expf(-tts) * expf(W_spk[s]);

        // history kernel = W_hist @ raised-cosine log-time basis
        float raw = 4.0f * logf(mf + 1.0f);
        float hk  = 0.0f;
        for (int c = 0; c < COS_NO; c++) {
            float phi = (PIF * 0.5f) * (float)c;
            if (raw >= phi - PIF && raw <= phi + PIF)
                hk += W_hist[s * COS_NO + c] * (0.5f * cosf(raw - phi) + 0.5f);
        }

        g_ek[i]   = ek;
        g_ik[i]   = ik;
        g_spkk[i] = sk;
        g_histk[i]= hk;

        // filter output: rows 0-19 e_kern, 20-39 i_kern, 40-59 spk_kern, 60-79 hist_kern
        filt_out[(0 * SUBN + s) * T_NO + m] = ek;
        filt_out[(1 * SUBN + s) * T_NO + m] = ik;
        filt_out[(2 * SUBN + s) * T_NO + m] = sk;
        filt_out[(3 * SUBN + s) * T_NO + m] = hk;
    }
}

// ---------------- K1: one-hot scatter-sum of spikes into subunit bins ----------------
__global__ void agg_kernel(const float* __restrict__ S_e,
                           const float* __restrict__ S_i)
{
    __shared__ float acc_e[SUBN];
    __shared__ float acc_i[SUBN];
    int t   = blockIdx.x;
    int tid = threadIdx.x;
    if (tid < SUBN) { acc_e[tid] = 0.0f; acc_i[tid] = 0.0f; }
    __syncthreads();

    const float* re = S_e + (size_t)t * E_NOC;
    for (int e = tid; e < E_NOC; e += blockDim.x) {
        float v = re[e];
        if (v != 0.0f) atomicAdd(&acc_e[g_idx_e[e]], v);   // v is exactly 1.0 -> exact sums
    }
    const float* ri = S_i + (size_t)t * I_NOC;
    for (int e = tid; e < I_NOC; e += blockDim.x) {
        float v = ri[e];
        if (v != 0.0f) atomicAdd(&acc_i[g_idx_i[e]], v);
    }
    __syncthreads();
    if (tid < SUBN) {
        g_se[t * SUBN + tid] = acc_e[tid];
        g_si[t * SUBN + tid] = acc_i[tid];
    }
}

// ---------------- K2: causal FIR of syn drive with e/i kernels ----------------
// syn[t][s] = sum_{m=0}^{199} ek[s][m]*se[t-1-m][s] + ik[s][m]*si[t-1-m][s]
#define CONV_TS 128
__global__ void conv_kernel()
{
    __shared__ float ek[SUBN * T_NO];
    __shared__ float ik[SUBN * T_NO];
    int tid = threadIdx.x;
    for (int i = tid; i < SUBN * T_NO; i += blockDim.x) {
        ek[i] = g_ek[i];
        ik[i] = g_ik[i];
    }
    __syncthreads();

    int t0 = blockIdx.x * CONV_TS;
    for (int w = tid; w < CONV_TS * SUBN; w += blockDim.x) {
        int tt = t0 + w / SUBN;
        int s  = w % SUBN;
        if (tt >= T_DATA) continue;
        int mmax = min(T_NO, tt);   // indices t-1-m >= 0  <=>  m <= tt-1
        float acc = 0.0f;
        const float* eks = ek + s * T_NO;
        const float* iks = ik + s * T_NO;
        for (int m = 0; m < mmax; m++) {
            int ti = tt - 1 - m;
            acc = fmaf(eks[m], g_se[ti * SUBN + s], acc);
            acc = fmaf(iks[m], g_si[ti * SUBN + s], acc);
        }
        g_syn[tt * SUBN + s] = acc;
    }
}

// ---------------- K3: sequential recurrence, one persistent block ----------------
// 20 warps, warp w owns subunit w. Ring buffer of spikes (256 deep, pitch 21
// for bank-conflict freedom). Per step: 200-tap dot for hist & spk per warp,
// butterfly reduce, warp0 does C_den matvec + threshold + sigmoid.
#define RING_PITCH 21
#define RECUR_THREADS 640
// shared floats: histk 4000 + spkk 4000 + ring 256*21 + synb 256*21 + shh 32 + shq 32
#define RECUR_SMEM_FLOATS (4000 + 4000 + 256*RING_PITCH + 256*RING_PITCH + 32 + 32)

__global__ void __launch_bounds__(RECUR_THREADS, 1)
recur_kernel(const float* __restrict__ C_den,
             const float* __restrict__ Theta,
             float* __restrict__ Z,
             float* __restrict__ P)
{
    extern __shared__ float sm[];
    float* histk = sm;                        // 4000
    float* spkk  = histk + 4000;              // 4000
    float* ring  = spkk + 4000;               // 256*21
    float* synb  = ring + 256 * RING_PITCH;   // 256*21
    float* shh   = synb + 256 * RING_PITCH;   // 32
    float* shq   = shh + 32;                  // 32

    int tid  = threadIdx.x;
    int w    = tid >> 5;
    int lane = tid & 31;
    int s    = w;   // subunit owned by this warp (w in 0..19)

    for (int i = tid; i < SUBN * T_NO; i += RECUR_THREADS) {
        histk[i] = g_histk[i];
        spkk[i]  = g_spkk[i];
    }
    for (int i = tid; i < 256 * RING_PITCH; i += RECUR_THREADS) ring[i] = 0.0f;

    // warp0 lanes cache their C_den row + theta in registers
    float cd[SUBN];
    float th = 0.0f;
    if (w == 0 && lane < SUBN) {
        #pragma unroll
        for (int j = 0; j < SUBN; j++) cd[j] = C_den[lane * SUBN + j];
        th = Theta[lane];
    }
    __syncthreads();

    const float* hks = histk + s * T_NO;
    const float* qks = spkk  + s * T_NO;

    for (int t = 0; t < T_DATA; t++) {
        if ((t & 255) == 0) {
            // bulk-stage the next 256 rows of filtered syn drive
            for (int i = tid; i < 256 * SUBN; i += RECUR_THREADS) {
                int r = i / SUBN, c = i % SUBN;
                int tt = t + r;
                synb[r * RING_PITCH + c] = (tt < T_DATA) ? g_syn[tt * SUBN + c] : 0.0f;
            }
            __syncthreads();
        }

        float h = 0.0f, q = 0.0f;
        #pragma unroll
        for (int j = 0; j < 7; j++) {
            int m = lane + 32 * j;
            if (j < 6 || lane < 8) {   // m < 200
                int idx = (t - 1 - m) & 255;
                float zv = ring[idx * RING_PITCH + s];
                h = fmaf(hks[m], zv, h);
                q = fmaf(qks[m], zv, q);
            }
        }
        #pragma unroll
        for (int o = 16; o > 0; o >>= 1) {
            h += __shfl_xor_sync(0xFFFFFFFFu, h, o);
            q += __shfl_xor_sync(0xFFFFFFFFu, q, o);
        }
        if (lane == 0) { shh[s] = h; shq[s] = q; }
        __syncthreads();

        if (w == 0 && lane < SUBN) {
            float sv = synb[(t & 255) * RING_PITCH + lane] + th + shh[lane];
            #pragma unroll
            for (int j = 0; j < SUBN; j++) sv = fmaf(cd[j], shq[j], sv);
            float z = (sv > 0.0f) ? 1.0f : 0.0f;   // heaviside(x, 0)
            ring[(t & 255) * RING_PITCH + lane] = z;
            Z[t * SUBN + lane] = z;
            P[t * SUBN + lane] = 1.0f / (1.0f + expf(-sv));
        }
        __syncthreads();
    }
}

// ---------------- launch ----------------
extern "C" void kernel_launch(void* const* d_in, const int* in_sizes, int n_in,
                              void* d_out, int out_size)
{
    const float* S_e       = (const float*)d_in[0];
    const float* S_i       = (const float*)d_in[1];
    const float* C_den     = (const float*)d_in[2];
    const float* C_syn_e   = (const float*)d_in[3];
    const float* C_syn_i   = (const float*)d_in[4];
    const float* Tau_syn   = (const float*)d_in[5];
    const float* Delta_syn = (const float*)d_in[6];
    const float* W_syn     = (const float*)d_in[7];
    const float* Tau_spk   = (const float*)d_in[8];
    const float* W_spk     = (const float*)d_in[9];
    const float* W_hist    = (const float*)d_in[10];
    const float* Theta     = (const float*)d_in[11];

    float* out = (float*)d_out;
    float* Z = out;                          // [10000, 20]
    float* P = out + T_DATA * SUBN;          // [10000, 20]
    float* F = out + 2 * T_DATA * SUBN;      // [80, 200]

    prep_kernel<<<1, 256>>>(C_syn_e, C_syn_i, Tau_syn, Delta_syn, W_syn,
                            Tau_spk, W_spk, W_hist, F);
    agg_kernel<<<T_DATA, 256>>>(S_e, S_i);
    conv_kernel<<<(T_DATA + CONV_TS - 1) / CONV_TS, 256>>>();

    cudaFuncSetAttribute(recur_kernel,
                         cudaFuncAttributeMaxDynamicSharedMemorySize,
                         RECUR_SMEM_FLOATS * (int)sizeof(float));
    recur_kernel<<<1, RECUR_THREADS, RECUR_SMEM_FLOATS * sizeof(float)>>>(C_den, Theta, Z, P);
}

// round 3
// speedup vs baseline: 1.5608x; 1.5607x over previous
#include <cuda_runtime.h>
#include <math.h>

#define T_NO   200
#define SUBN   20
#define E_NOC  2000
#define I_NOC  500
#define T_DATA 10000
#define COS_NO 17
#define R_FIX  4          // taps handled serially by the leader
#define NTAPS  13         // ceil(196/16) taps per partial lane

// ---------------- device scratch (static allocation only) ----------------
__device__ float g_se[T_DATA * SUBN];
__device__ float g_si[T_DATA * SUBN];
__device__ float g_syn[T_DATA * SUBN];
__device__ float g_sv[T_DATA * SUBN];     // raw pre-activation, consumed by zp_kernel
__device__ float g_ek[SUBN * T_NO];
__device__ float g_ik[SUBN * T_NO];
__device__ float g_spkk[SUBN * T_NO];
__device__ float g_histk[SUBN * T_NO];
__device__ int   g_idx_e[E_NOC];
__device__ int   g_idx_i[I_NOC];

// ---------------- K0: indices + all kernels + filter output ----------------
__global__ void prep_kernel(const float* __restrict__ C_syn_e,
                            const float* __restrict__ C_syn_i,
                            const float* __restrict__ Tau_syn,
                            const float* __restrict__ Delta_syn,
                            const float* __restrict__ W_syn,
                            const float* __restrict__ Tau_spk,
                            const float* __restrict__ W_spk,
                            const float* __restrict__ W_hist,
                            float* __restrict__ filt_out)
{
    int tid = threadIdx.x;
    int nt  = blockDim.x;

    for (int e = tid; e < E_NOC; e += nt) {
        int k = 0;
        for (int s = 0; s < SUBN; s++)
            if (C_syn_e[s * E_NOC + e] > 0.5f) k = s;
        g_idx_e[e] = k;
    }
    for (int e = tid; e < I_NOC; e += nt) {
        int k = 0;
        for (int s = 0; s < SUBN; s++)
            if (C_syn_i[s * I_NOC + e] > 0.5f) k = s;
        g_idx_i[e] = k;
    }

    const float PIF = 3.14159265358979323846f;
    for (int i = tid; i < SUBN * T_NO; i += nt) {
        int s = i / T_NO;
        int m = i % T_NO;
        float mf = (float)m;

        float te  = fmaxf(mf - expf(Delta_syn[s * 2 + 0]), 0.0f);
        float tte = te / expf(Tau_syn[s * 2 + 0]);
        float ek  = tte * expf(-tte) * expf(W_syn[s * 2 + 0]);

        float td  = fmaxf(mf - expf(Delta_syn[s * 2 + 1]), 0.0f);
        float tti = td / expf(Tau_syn[s * 2 + 1]);
        float ik  = -tti * expf(-tti) * expf(W_syn[s * 2 + 1]);

        float tts = mf / expf(Tau_spk[s]);
        float sk  = tts * expf(-tts) * expf(W_spk[s]);

        float raw = 4.0f * logf(mf + 1.0f);
        float hk  = 0.0f;
        for (int c = 0; c < COS_NO; c++) {
            float phi = (PIF * 0.5f) * (float)c;
            if (raw >= phi - PIF && raw <= phi + PIF)
                hk += W_hist[s * COS_NO + c] * (0.5f * cosf(raw - phi) + 0.5f);
        }

        g_ek[i]    = ek;
        g_ik[i]    = ik;
        g_spkk[i]  = sk;
        g_histk[i] = hk;

        filt_out[(0 * SUBN + s) * T_NO + m] = ek;
        filt_out[(1 * SUBN + s) * T_NO + m] = ik;
        filt_out[(2 * SUBN + s) * T_NO + m] = sk;
        filt_out[(3 * SUBN + s) * T_NO + m] = hk;
    }
}

// ---------------- K1: one-hot scatter-sum of spikes into subunit bins ----------------
__global__ void agg_kernel(const float* __restrict__ S_e,
                           const float* __restrict__ S_i)
{
    __shared__ float acc_e[SUBN];
    __shared__ float acc_i[SUBN];
    int t   = blockIdx.x;
    int tid = threadIdx.x;
    if (tid < SUBN) { acc_e[tid] = 0.0f; acc_i[tid] = 0.0f; }
    __syncthreads();

    const float* re = S_e + (size_t)t * E_NOC;
    for (int e = tid; e < E_NOC; e += blockDim.x) {
        float v = re[e];
        if (v != 0.0f) atomicAdd(&acc_e[g_idx_e[e]], v);
    }
    const float* ri = S_i + (size_t)t * I_NOC;
    for (int e = tid; e < I_NOC; e += blockDim.x) {
        float v = ri[e];
        if (v != 0.0f) atomicAdd(&acc_i[g_idx_i[e]], v);
    }
    __syncthreads();
    if (tid < SUBN) {
        g_se[t * SUBN + tid] = acc_e[tid];
        g_si[t * SUBN + tid] = acc_i[tid];
    }
}

// ---------------- K2: causal FIR, fully smem-staged ----------------
// syn[t][s] = sum_{m=0}^{min(200,t)-1} ek[s][m]*se[t-1-m][s] + ik[s][m]*si[t-1-m][s]
#define CONV_TS 256
#define CONV_THREADS 512
#define CONV_ROWS (CONV_TS + T_NO)             // 456 staged rows
// floats: ek 4000 + ik 4000 + se 456*20 + si 456*20 = 26240
#define CONV_SMEM_FLOATS (4000 + 4000 + CONV_ROWS*SUBN + CONV_ROWS*SUBN)

__global__ void __launch_bounds__(CONV_THREADS, 1) conv_kernel()
{
    extern __shared__ float cs[];
    float* ek   = cs;
    float* ik   = ek + 4000;
    float* se_s = ik + 4000;
    float* si_s = se_s + CONV_ROWS * SUBN;

    int tid = threadIdx.x;
    int t0  = blockIdx.x * CONV_TS;

    for (int i = tid; i < SUBN * T_NO; i += CONV_THREADS) {
        ek[i] = g_ek[i];
        ik[i] = g_ik[i];
    }
    for (int i = tid; i < CONV_ROWS * SUBN; i += CONV_THREADS) {
        int r  = i / SUBN;
        int s  = i % SUBN;
        int tg = t0 - T_NO + r;
        float ve = 0.0f, vi = 0.0f;
        if (tg >= 0 && tg < T_DATA) {
            ve = g_se[tg * SUBN + s];
            vi = g_si[tg * SUBN + s];
        }
        se_s[i] = ve;
        si_s[i] = vi;
    }
    __syncthreads();

    for (int wi = tid; wi < CONV_TS * SUBN; wi += CONV_THREADS) {
        int tt = t0 + wi / SUBN;
        int s  = wi % SUBN;
        if (tt >= T_DATA) continue;
        int mmax = min(T_NO, tt);
        // local row for m: (tt - 1 - m) - (t0 - T_NO) = (tt - t0 + T_NO - 1) - m
        int base = ((tt - t0 + T_NO - 1) * SUBN) + s;
        const float* eks = ek + s * T_NO;
        const float* iks = ik + s * T_NO;
        float a0 = 0.0f, a1 = 0.0f;
        for (int m = 0; m < mmax; m++) {
            int ai = base - m * SUBN;
            a0 = fmaf(eks[m], se_s[ai], a0);
            a1 = fmaf(iks[m], si_s[ai], a1);
        }
        g_syn[tt * SUBN + s] = a0 + a1;
    }
}

// ---------------- K3: pipelined recurrence ----------------
// Warp 0 = leader (lane s = subunit). Warps 1..10 = partial warps, each owns
// 2 subunits (16 lanes each), computing the m>=4 portion of the 200-tap dot
// for step t+4 during step t. Leader per-step path: read partials, 4-tap
// register fixup, C_den matvec via smem broadcast + product tree, threshold.
// Sigmoid moved to zp_kernel. ONE __syncthreads per step.
#define RING_PITCH 21
#define RECUR_THREADS 352   // 11 warps

__global__ void __launch_bounds__(RECUR_THREADS, 1)
recur_kernel(const float* __restrict__ C_den,
             const float* __restrict__ Theta)
{
    __shared__ float ring[256 * RING_PITCH];   // z history, slot = t & 255
    __shared__ float synb[256 * SUBN];         // staged syn drive chunk
    __shared__ float Hpart[8 * SUBN];          // published partial hist dots
    __shared__ float Qpart[8 * SUBN];          // published partial spk dots
    __shared__ float shq[32];                  // current-step q per subunit

    int tid  = threadIdx.x;
    int w    = tid >> 5;
    int lane = tid & 31;

    for (int i = tid; i < 256 * RING_PITCH; i += RECUR_THREADS) ring[i] = 0.0f;
    for (int i = tid; i < 8 * SUBN; i += RECUR_THREADS) { Hpart[i] = 0.0f; Qpart[i] = 0.0f; }
    if (tid < 32) shq[tid] = 0.0f;

    // ---- leader registers ----
    float cd[SUBN];
    float th = 0.0f;
    float kh0 = 0, kh1 = 0, kh2 = 0, kh3 = 0;
    float kq0 = 0, kq1 = 0, kq2 = 0, kq3 = 0;
    float z1 = 0, z2 = 0, z3 = 0, z4 = 0;
    if (w == 0 && lane < SUBN) {
        #pragma unroll
        for (int j = 0; j < SUBN; j++) cd[j] = C_den[lane * SUBN + j];
        th  = Theta[lane];
        kh0 = g_histk[lane * T_NO + 0]; kh1 = g_histk[lane * T_NO + 1];
        kh2 = g_histk[lane * T_NO + 2]; kh3 = g_histk[lane * T_NO + 3];
        kq0 = g_spkk [lane * T_NO + 0]; kq1 = g_spkk [lane * T_NO + 1];
        kq2 = g_spkk [lane * T_NO + 2]; kq3 = g_spkk [lane * T_NO + 3];
    }

    // ---- partial-warp registers ----
    int sP = 0, lP = 0;
    float kh[NTAPS], kq[NTAPS];
    if (w >= 1) {
        sP = (w - 1) * 2 + (lane >> 4);   // subunit handled by this half-warp
        lP = lane & 15;
        #pragma unroll
        for (int j = 0; j < NTAPS; j++) {
            int m = R_FIX + lP + 16 * j;
            kh[j] = (m < T_NO) ? g_histk[sP * T_NO + m] : 0.0f;
            kq[j] = (m < T_NO) ? g_spkk [sP * T_NO + m] : 0.0f;
        }
    }
    __syncthreads();

    for (int t = 0; t < T_DATA; t++) {
        if ((t & 255) == 0) {
            for (int i = tid; i < 256 * SUBN; i += RECUR_THREADS) {
                int tt = t + i / SUBN;
                synb[i] = (tt < T_DATA) ? g_syn[tt * SUBN + (i % SUBN)] : 0.0f;
            }
            __syncthreads();
        }

        if (w == 0) {
            float q = 0.0f, h = 0.0f;
            if (lane < SUBN) {
                h = Hpart[(t & 7) * SUBN + lane];
                q = Qpart[(t & 7) * SUBN + lane];
                h += (kh0 * z1 + kh1 * z2) + (kh2 * z3 + kh3 * z4);
                q += (kq0 * z1 + kq1 * z2) + (kq2 * z3 + kq3 * z4);
                shq[lane] = q;
            }
            __syncwarp();
            if (lane < SUBN) {
                float pr[SUBN];
                #pragma unroll
                for (int j = 0; j < SUBN; j++) pr[j] = cd[j] * shq[j];
                float s0 = (pr[0] + pr[1]) + (pr[2] + pr[3]);
                float s1 = (pr[4] + pr[5]) + (pr[6] + pr[7]);
                float s2 = (pr[8] + pr[9]) + (pr[10] + pr[11]);
                float s3 = (pr[12] + pr[13]) + (pr[14] + pr[15]);
                float s4 = (pr[16] + pr[17]) + (pr[18] + pr[19]);
                float sv = (synb[(t & 255) * SUBN + lane] + th) + h
                         + ((s0 + s1) + (s2 + (s3 + s4)));
                float z = (sv > 0.0f) ? 1.0f : 0.0f;
                z4 = z3; z3 = z2; z2 = z1; z1 = z;
                ring[(t & 255) * RING_PITCH + lane] = z;
                g_sv[t * SUBN + lane] = sv;
            }
        } else {
            // partial dot for step u = t + R_FIX over taps m = R_FIX..199
            int u    = t + R_FIX;
            int base = t - 1 - lP;            // time index of tap j=0
            float h0 = 0.0f, h1 = 0.0f, q0 = 0.0f, q1 = 0.0f;
            #pragma unroll
            for (int j = 0; j < NTAPS; j++) {
                int slot = (base - 16 * j) & 255;
                float zv = ring[slot * RING_PITCH + sP];
                if (j & 1) { h1 = fmaf(kh[j], zv, h1); q1 = fmaf(kq[j], zv, q1); }
                else       { h0 = fmaf(kh[j], zv, h0); q0 = fmaf(kq[j], zv, q0); }
            }
            float h = h0 + h1, q = q0 + q1;
            #pragma unroll
            for (int o = 8; o > 0; o >>= 1) {
                h += __shfl_xor_sync(0xFFFFFFFFu, h, o);
                q += __shfl_xor_sync(0xFFFFFFFFu, q, o);
            }
            if (lP == 0) {
                Hpart[(u & 7) * SUBN + sP] = h;
                Qpart[(u & 7) * SUBN + sP] = q;
            }
        }
        __syncthreads();
    }
}

// ---------------- K4: Z/P from raw pre-activations ----------------
__global__ void zp_kernel(float* __restrict__ Z, float* __restrict__ P)
{
    int idx = blockIdx.x * blockDim.x + threadIdx.x;
    if (idx < T_DATA * SUBN) {
        float sv = g_sv[idx];
        Z[idx] = (sv > 0.0f) ? 1.0f : 0.0f;
        P[idx] = 1.0f / (1.0f + expf(-sv));
    }
}

// ---------------- launch ----------------
extern "C" void kernel_launch(void* const* d_in, const int* in_sizes, int n_in,
                              void* d_out, int out_size)
{
    const float* S_e       = (const float*)d_in[0];
    const float* S_i       = (const float*)d_in[1];
    const float* C_den     = (const float*)d_in[2];
    const float* C_syn_e   = (const float*)d_in[3];
    const float* C_syn_i   = (const float*)d_in[4];
    const float* Tau_syn   = (const float*)d_in[5];
    const float* Delta_syn = (const float*)d_in[6];
    const float* W_syn     = (const float*)d_in[7];
    const float* Tau_spk   = (const float*)d_in[8];
    const float* W_spk     = (const float*)d_in[9];
    const float* W_hist    = (const float*)d_in[10];
    const float* Theta     = (const float*)d_in[11];

    float* out = (float*)d_out;
    float* Z = out;                          // [10000, 20]
    float* P = out + T_DATA * SUBN;          // [10000, 20]
    float* F = out + 2 * T_DATA * SUBN;      // [80, 200]

    prep_kernel<<<1, 256>>>(C_syn_e, C_syn_i, Tau_syn, Delta_syn, W_syn,
                            Tau_spk, W_spk, W_hist, F);
    agg_kernel<<<T_DATA, 256>>>(S_e, S_i);

    cudaFuncSetAttribute(conv_kernel,
                         cudaFuncAttributeMaxDynamicSharedMemorySize,
                         CONV_SMEM_FLOATS * (int)sizeof(float));
    conv_kernel<<<(T_DATA + CONV_TS - 1) / CONV_TS, CONV_THREADS,
                  CONV_SMEM_FLOATS * sizeof(float)>>>();

    recur_kernel<<<1, RECUR_THREADS>>>(C_den, Theta);

    zp_kernel<<<(T_DATA * SUBN + 255) / 256, 256>>>(Z, P);
}

// round 4
// speedup vs baseline: 1.7722x; 1.1354x over previous
#include <cuda_runtime.h>
#include <math.h>

#define T_NO   200
#define SUBN   20
#define E_NOC  2000
#define I_NOC  500
#define T_DATA 10000
#define COS_NO 17

// ---------------- device scratch (static allocation only) ----------------
__device__ float g_se[T_DATA * SUBN];
__device__ float g_si[T_DATA * SUBN];
__device__ float g_syn[T_DATA * SUBN];    // filtered drive + Theta folded in
__device__ float g_sv[T_DATA * SUBN];     // raw pre-activation
__device__ float g_ek[SUBN * T_NO];
__device__ float g_ik[SUBN * T_NO];
__device__ float g_spkk[SUBN * T_NO];
__device__ float g_histk[SUBN * T_NO];
__device__ int   g_idx_e[E_NOC];
__device__ int   g_idx_i[I_NOC];

// ---------------- K0: indices + all kernels + filter output ----------------
__global__ void prep_kernel(const float* __restrict__ C_syn_e,
                            const float* __restrict__ C_syn_i,
                            const float* __restrict__ Tau_syn,
                            const float* __restrict__ Delta_syn,
                            const float* __restrict__ W_syn,
                            const float* __restrict__ Tau_spk,
                            const float* __restrict__ W_spk,
                            const float* __restrict__ W_hist,
                            float* __restrict__ filt_out)
{
    int tid = threadIdx.x;
    int nt  = blockDim.x;

    for (int e = tid; e < E_NOC; e += nt) {
        int k = 0;
        for (int s = 0; s < SUBN; s++)
            if (C_syn_e[s * E_NOC + e] > 0.5f) k = s;
        g_idx_e[e] = k;
    }
    for (int e = tid; e < I_NOC; e += nt) {
        int k = 0;
        for (int s = 0; s < SUBN; s++)
            if (C_syn_i[s * I_NOC + e] > 0.5f) k = s;
        g_idx_i[e] = k;
    }

    const float PIF = 3.14159265358979323846f;
    for (int i = tid; i < SUBN * T_NO; i += nt) {
        int s = i / T_NO;
        int m = i % T_NO;
        float mf = (float)m;

        float te  = fmaxf(mf - expf(Delta_syn[s * 2 + 0]), 0.0f);
        float tte = te / expf(Tau_syn[s * 2 + 0]);
        float ek  = tte * expf(-tte) * expf(W_syn[s * 2 + 0]);

        float td  = fmaxf(mf - expf(Delta_syn[s * 2 + 1]), 0.0f);
        float tti = td / expf(Tau_syn[s * 2 + 1]);
        float ik  = -tti * expf(-tti) * expf(W_syn[s * 2 + 1]);

        float tts = mf / expf(Tau_spk[s]);
        float sk  = tts * expf(-tts) * expf(W_spk[s]);

        float raw = 4.0f * logf(mf + 1.0f);
        float hk  = 0.0f;
        for (int c = 0; c < COS_NO; c++) {
            float phi = (PIF * 0.5f) * (float)c;
            if (raw >= phi - PIF && raw <= phi + PIF)
                hk += W_hist[s * COS_NO + c] * (0.5f * cosf(raw - phi) + 0.5f);
        }

        g_ek[i]    = ek;
        g_ik[i]    = ik;
        g_spkk[i]  = sk;
        g_histk[i] = hk;

        filt_out[(0 * SUBN + s) * T_NO + m] = ek;
        filt_out[(1 * SUBN + s) * T_NO + m] = ik;
        filt_out[(2 * SUBN + s) * T_NO + m] = sk;
        filt_out[(3 * SUBN + s) * T_NO + m] = hk;
    }
}

// ---------------- K1: one-hot scatter-sum ----------------
__global__ void agg_kernel(const float* __restrict__ S_e,
                           const float* __restrict__ S_i)
{
    __shared__ float acc_e[SUBN];
    __shared__ float acc_i[SUBN];
    int t   = blockIdx.x;
    int tid = threadIdx.x;
    if (tid < SUBN) { acc_e[tid] = 0.0f; acc_i[tid] = 0.0f; }
    __syncthreads();

    const float* re = S_e + (size_t)t * E_NOC;
    for (int e = tid; e < E_NOC; e += blockDim.x) {
        float v = re[e];
        if (v != 0.0f) atomicAdd(&acc_e[g_idx_e[e]], v);
    }
    const float* ri = S_i + (size_t)t * I_NOC;
    for (int e = tid; e < I_NOC; e += blockDim.x) {
        float v = ri[e];
        if (v != 0.0f) atomicAdd(&acc_i[g_idx_i[e]], v);
    }
    __syncthreads();
    if (tid < SUBN) {
        g_se[t * SUBN + tid] = acc_e[tid];
        g_si[t * SUBN + tid] = acc_i[tid];
    }
}

// ---------------- K2: causal FIR, smem-staged, Theta folded in ----------------
#define CONV_TS 256
#define CONV_THREADS 512
#define CONV_ROWS (CONV_TS + T_NO)
#define CONV_SMEM_FLOATS (4000 + 4000 + CONV_ROWS*SUBN + CONV_ROWS*SUBN)

__global__ void __launch_bounds__(CONV_THREADS, 1)
conv_kernel(const float* __restrict__ Theta)
{
    extern __shared__ float cs[];
    float* ek   = cs;
    float* ik   = ek + 4000;
    float* se_s = ik + 4000;
    float* si_s = se_s + CONV_ROWS * SUBN;

    int tid = threadIdx.x;
    int t0  = blockIdx.x * CONV_TS;

    for (int i = tid; i < SUBN * T_NO; i += CONV_THREADS) {
        ek[i] = g_ek[i];
        ik[i] = g_ik[i];
    }
    for (int i = tid; i < CONV_ROWS * SUBN; i += CONV_THREADS) {
        int r  = i / SUBN;
        int s  = i % SUBN;
        int tg = t0 - T_NO + r;
        float ve = 0.0f, vi = 0.0f;
        if (tg >= 0 && tg < T_DATA) {
            ve = g_se[tg * SUBN + s];
            vi = g_si[tg * SUBN + s];
        }
        se_s[i] = ve;
        si_s[i] = vi;
    }
    __syncthreads();

    for (int wi = tid; wi < CONV_TS * SUBN; wi += CONV_THREADS) {
        int tt = t0 + wi / SUBN;
        int s  = wi % SUBN;
        if (tt >= T_DATA) continue;
        int mmax = min(T_NO, tt);
        int base = ((tt - t0 + T_NO - 1) * SUBN) + s;
        const float* eks = ek + s * T_NO;
        const float* iks = ik + s * T_NO;
        float a0 = 0.0f, a1 = 0.0f;
        for (int m = 0; m < mmax; m++) {
            int ai = base - m * SUBN;
            a0 = fmaf(eks[m], se_s[ai], a0);
            a1 = fmaf(iks[m], si_s[ai], a1);
        }
        g_syn[tt * SUBN + s] = a0 + a1 + Theta[s];
    }
}

// ---------------- K3: pipelined recurrence, 8 warps, 1 barrier/step ----------------
// warp 0: leader       sv[i] = E[t][i] + hist(m=0..3 fixup); z; ring write
// warp 1: spk+matvec   q via exact 2-state recurrence; G=C_den@q; E[t+1]
// warp 2: sum+stage    reduce 8 raw hist partials -> Hpart; stage synb rows
// warp 3-7: hist partials, taps m>=4, 8 lanes/subunit, 25 interleaved taps
#define RING_PITCH 21
#define NP_TAPS 25
#define RECUR_THREADS 256

// shared layout (floats):
#define OFF_RING 0                            // [512][21] doubled ring
#define OFF_SYNB (OFF_RING + 512*RING_PITCH)  // [256][20]
#define OFF_PRAW (OFF_SYNB + 256*SUBN)        // [4][160]
#define OFF_HP   (OFF_PRAW + 4*160)           // [8][20]
#define OFF_EB   (OFF_HP + 8*SUBN)            // [2][32]
#define OFF_SHQ  (OFF_EB + 64)                // [32]
#define RECUR_SMEM_FLOATS (OFF_SHQ + 32)

__global__ void __launch_bounds__(RECUR_THREADS, 1)
recur_kernel(const float* __restrict__ C_den,
             const float* __restrict__ Tau_spk,
             const float* __restrict__ W_spk)
{
    extern __shared__ float sm[];
    float* ring  = sm + OFF_RING;
    float* synb  = sm + OFF_SYNB;
    float* Praw  = sm + OFF_PRAW;
    float* Hpart = sm + OFF_HP;
    float* Eb    = sm + OFF_EB;
    float* shq   = sm + OFF_SHQ;

    int tid  = threadIdx.x;
    int w    = tid >> 5;
    int lane = tid & 31;

    // ---- zero init ----
    for (int i = tid; i < RECUR_SMEM_FLOATS; i += RECUR_THREADS) sm[i] = 0.0f;
    __syncthreads();

    // pre-stage synb rows 0..63 ; E[0] = syn[0] (+Theta already folded)
    for (int i = tid; i < 64 * SUBN; i += RECUR_THREADS) synb[i] = g_syn[i];
    if (tid < SUBN) Eb[tid] = g_syn[tid];

    // ---- per-role registers ----
    // leader
    float kh0 = 0, kh1 = 0, kh2 = 0, kh3 = 0;
    float z1 = 0, z2 = 0, z3 = 0, z4 = 0;
    if (w == 0 && lane < SUBN) {
        kh0 = g_histk[lane * T_NO + 0];
        kh1 = g_histk[lane * T_NO + 1];
        kh2 = g_histk[lane * T_NO + 2];
        kh3 = g_histk[lane * T_NO + 3];
    }

    // helper (spk recurrence + matvec)
    float rr = 0, cc = 0, U = 0, V = 0;
    float cd[SUBN];
    if (w == 1 && lane < SUBN) {
        rr = expf(-expf(-Tau_spk[lane]));            // r = exp(-1/tau)
        cc = expf(W_spk[lane] - Tau_spk[lane]);      // c = exp(W)/tau
        #pragma unroll
        for (int j = 0; j < SUBN; j++) cd[j] = C_den[lane * SUBN + j];
    }

    // sum+stage warp: 4-deep LDG pipeline for synb staging
    float sr0 = 0, sr1 = 0, sr2 = 0, sr3 = 0;
    if (w == 2 && lane < SUBN) {
        sr0 = g_syn[64 * SUBN + lane];
        sr1 = g_syn[65 * SUBN + lane];
        sr2 = g_syn[66 * SUBN + lane];
        sr3 = g_syn[67 * SUBN + lane];
    }

    // hist partial warps
    int L = 0, sP = 0, lP = 0;
    float kh[NP_TAPS];
    if (w >= 3) {
        L  = (w - 3) * 32 + lane;       // 0..159
        sP = L >> 3;                    // subunit
        lP = L & 7;
        #pragma unroll
        for (int j = 0; j < NP_TAPS; j++) {
            int m = 4 + lP + 8 * j;
            kh[j] = (m < T_NO) ? g_histk[sP * T_NO + m] : 0.0f;
        }
    }
    __syncthreads();

    for (int t = 0; t < T_DATA; t++) {
        if (w == 0) {
            // ---------------- leader ----------------
            if (lane < SUBN) {
                float sv = Eb[(t & 1) * 32 + lane];
                sv = fmaf(kh0, z1, sv);
                sv = fmaf(kh1, z2, sv);
                sv = fmaf(kh2, z3, sv);
                sv = fmaf(kh3, z4, sv);
                float z = (sv > 0.0f) ? 1.0f : 0.0f;
                int slot = t & 255;
                ring[slot * RING_PITCH + lane] = z;
                ring[(slot + 256) * RING_PITCH + lane] = z;
                g_sv[t * SUBN + lane] = sv;
                z4 = z3; z3 = z2; z2 = z1; z1 = z;
            }
        } else if (w == 1) {
            // ---------------- helper: q[t+1] + matvec + E[t+1] ----------------
            if (lane < SUBN) {
                float zprev = ring[((t - 1) & 255) * RING_PITCH + lane]; // z[t-1]
                U = fmaf(rr, U, zprev);     // u[t]
                V = rr * (V + U);           // v[t+1]
                shq[lane] = cc * V;         // q[t+1]
            }
            __syncwarp();
            if (lane < SUBN) {
                const float4* qv = (const float4*)shq;
                float4 q0 = qv[0], q1 = qv[1], q2 = qv[2], q3 = qv[3], q4 = qv[4];
                float G = 0.0f;
                G = fmaf(cd[0],  q0.x, G); G = fmaf(cd[1],  q0.y, G);
                G = fmaf(cd[2],  q0.z, G); G = fmaf(cd[3],  q0.w, G);
                G = fmaf(cd[4],  q1.x, G); G = fmaf(cd[5],  q1.y, G);
                G = fmaf(cd[6],  q1.z, G); G = fmaf(cd[7],  q1.w, G);
                G = fmaf(cd[8],  q2.x, G); G = fmaf(cd[9],  q2.y, G);
                G = fmaf(cd[10], q2.z, G); G = fmaf(cd[11], q2.w, G);
                G = fmaf(cd[12], q3.x, G); G = fmaf(cd[13], q3.y, G);
                G = fmaf(cd[14], q3.z, G); G = fmaf(cd[15], q3.w, G);
                G = fmaf(cd[16], q4.x, G); G = fmaf(cd[17], q4.y, G);
                G = fmaf(cd[18], q4.z, G); G = fmaf(cd[19], q4.w, G);
                float Eo = G + Hpart[((t + 1) & 7) * SUBN + lane]
                             + synb[((t + 1) & 255) * SUBN + lane];
                Eb[((t + 1) & 1) * 32 + lane] = Eo;
            }
        } else if (w == 2) {
            // ---------------- sum (Hpart for u=t+3) + synb staging ----------------
            if (lane < SUBN) {
                int s4 = (t + 3) & 3;
                const float4* pr = (const float4*)&Praw[s4 * 160 + lane * 8];
                float4 x = pr[0], y = pr[1];
                float h = ((x.x + x.y) + (x.z + x.w)) + ((y.x + y.y) + (y.z + y.w));
                Hpart[((t + 3) & 7) * SUBN + lane] = h;

                // stage row t+64 (loaded 4 steps ago), fetch row t+68
                synb[((t + 64) & 255) * SUBN + lane] = sr0;
                sr0 = sr1; sr1 = sr2; sr2 = sr3;
                int rowg = t + 68;
                sr3 = (rowg < T_DATA) ? g_syn[rowg * SUBN + lane] : 0.0f;
            }
        } else {
            // ---------------- hist partials for u = t+4, taps m>=4 ----------------
            int B = ((t - 1 - lP) & 255) + 256;
            const float* p = &ring[B * RING_PITCH + sP];
            float a0 = 0, a1 = 0, a2 = 0, a3 = 0;
            #pragma unroll
            for (int j = 0; j < NP_TAPS; j++) {
                float zv = p[-(8 * RING_PITCH) * j];   // compile-time imm offsets
                if ((j & 3) == 0) a0 = fmaf(kh[j], zv, a0);
                else if ((j & 3) == 1) a1 = fmaf(kh[j], zv, a1);
                else if ((j & 3) == 2) a2 = fmaf(kh[j], zv, a2);
                else a3 = fmaf(kh[j], zv, a3);
            }
            Praw[(t & 3) * 160 + L] = (a0 + a1) + (a2 + a3);
        }
        __syncthreads();
    }
}

// ---------------- K4: Z/P from raw pre-activations ----------------
__global__ void zp_kernel(float* __restrict__ Z, float* __restrict__ P)
{
    int idx = blockIdx.x * blockDim.x + threadIdx.x;
    if (idx < T_DATA * SUBN) {
        float sv = g_sv[idx];
        Z[idx] = (sv > 0.0f) ? 1.0f : 0.0f;
        P[idx] = 1.0f / (1.0f + expf(-sv));
    }
}

// ---------------- launch ----------------
extern "C" void kernel_launch(void* const* d_in, const int* in_sizes, int n_in,
                              void* d_out, int out_size)
{
    const float* S_e       = (const float*)d_in[0];
    const float* S_i       = (const float*)d_in[1];
    const float* C_den     = (const float*)d_in[2];
    const float* C_syn_e   = (const float*)d_in[3];
    const float* C_syn_i   = (const float*)d_in[4];
    const float* Tau_syn   = (const float*)d_in[5];
    const float* Delta_syn = (const float*)d_in[6];
    const float* W_syn     = (const float*)d_in[7];
    const float* Tau_spk   = (const float*)d_in[8];
    const float* W_spk     = (const float*)d_in[9];
    const float* W_hist    = (const float*)d_in[10];
    const float* Theta     = (const float*)d_in[11];

    float* out = (float*)d_out;
    float* Z = out;                          // [10000, 20]
    float* P = out + T_DATA * SUBN;          // [10000, 20]
    float* F = out + 2 * T_DATA * SUBN;      // [80, 200]

    prep_kernel<<<1, 256>>>(C_syn_e, C_syn_i, Tau_syn, Delta_syn, W_syn,
                            Tau_spk, W_spk, W_hist, F);
    agg_kernel<<<T_DATA, 256>>>(S_e, S_i);

    cudaFuncSetAttribute(conv_kernel,
                         cudaFuncAttributeMaxDynamicSharedMemorySize,
                         CONV_SMEM_FLOATS * (int)sizeof(float));
    conv_kernel<<<(T_DATA + CONV_TS - 1) / CONV_TS, CONV_THREADS,
                  CONV_SMEM_FLOATS * sizeof(float)>>>(Theta);

    cudaFuncSetAttribute(recur_kernel,
                         cudaFuncAttributeMaxDynamicSharedMemorySize,
                         RECUR_SMEM_FLOATS * (int)sizeof(float));
    recur_kernel<<<1, RECUR_THREADS, RECUR_SMEM_FLOATS * sizeof(float)>>>(
        C_den, Tau_spk, W_spk);

    zp_kernel<<<(T_DATA * SUBN + 255) / 256, 256>>>(Z, P);
}

// round 5
// speedup vs baseline: 1.8893x; 1.0661x over previous
#include <cuda_runtime.h>
#include <math.h>

#define T_NO   200
#define SUBN   20
#define E_NOC  2000
#define I_NOC  500
#define T_DATA 10000
#define COS_NO 17
#define BW     32                       // recurrence block size
#define NBLK   ((T_DATA + BW - 1) / BW) // 313

// ---------------- device scratch (static allocation only) ----------------
__device__ float g_se[T_DATA * SUBN];
__device__ float g_si[T_DATA * SUBN];
__device__ float g_syn[T_DATA * SUBN];    // filtered drive + Theta folded in
__device__ float g_sv[T_DATA * SUBN];     // raw pre-activation
__device__ float g_ek[SUBN * T_NO];
__device__ float g_ik[SUBN * T_NO];
__device__ float g_spkk[SUBN * T_NO];
__device__ float g_histk[SUBN * T_NO];
__device__ float g_lut[SUBN * 1024];      // 4 x 256-entry byte LUTs per subunit (near hist)
__device__ int   g_idx_e[E_NOC];
__device__ int   g_idx_i[I_NOC];

// ---------------- K0: indices + kernels + LUT + filter output ----------------
__global__ void prep_kernel(const float* __restrict__ C_syn_e,
                            const float* __restrict__ C_syn_i,
                            const float* __restrict__ Tau_syn,
                            const float* __restrict__ Delta_syn,
                            const float* __restrict__ W_syn,
                            const float* __restrict__ Tau_spk,
                            const float* __restrict__ W_spk,
                            const float* __restrict__ W_hist,
                            float* __restrict__ filt_out)
{
    int tid = threadIdx.x;
    int nt  = blockDim.x;

    for (int e = tid; e < E_NOC; e += nt) {
        int k = 0;
        for (int s = 0; s < SUBN; s++)
            if (C_syn_e[s * E_NOC + e] > 0.5f) k = s;
        g_idx_e[e] = k;
    }
    for (int e = tid; e < I_NOC; e += nt) {
        int k = 0;
        for (int s = 0; s < SUBN; s++)
            if (C_syn_i[s * I_NOC + e] > 0.5f) k = s;
        g_idx_i[e] = k;
    }

    const float PIF = 3.14159265358979323846f;
    for (int i = tid; i < SUBN * T_NO; i += nt) {
        int s = i / T_NO;
        int m = i % T_NO;
        float mf = (float)m;

        float te  = fmaxf(mf - expf(Delta_syn[s * 2 + 0]), 0.0f);
        float tte = te / expf(Tau_syn[s * 2 + 0]);
        float ek  = tte * expf(-tte) * expf(W_syn[s * 2 + 0]);

        float td  = fmaxf(mf - expf(Delta_syn[s * 2 + 1]), 0.0f);
        float tti = td / expf(Tau_syn[s * 2 + 1]);
        float ik  = -tti * expf(-tti) * expf(W_syn[s * 2 + 1]);

        float tts = mf / expf(Tau_spk[s]);
        float sk  = tts * expf(-tts) * expf(W_spk[s]);

        float raw = 4.0f * logf(mf + 1.0f);
        float hk  = 0.0f;
        for (int c = 0; c < COS_NO; c++) {
            float phi = (PIF * 0.5f) * (float)c;
            if (raw >= phi - PIF && raw <= phi + PIF)
                hk += W_hist[s * COS_NO + c] * (0.5f * cosf(raw - phi) + 0.5f);
        }

        g_ek[i]    = ek;
        g_ik[i]    = ik;
        g_spkk[i]  = sk;
        g_histk[i] = hk;

        filt_out[(0 * SUBN + s) * T_NO + m] = ek;
        filt_out[(1 * SUBN + s) * T_NO + m] = ik;
        filt_out[(2 * SUBN + s) * T_NO + m] = sk;
        filt_out[(3 * SUBN + s) * T_NO + m] = hk;
    }
    __syncthreads();

    // near-hist LUTs: lut[s][k][b] = sum over set bits i of b of histk[s][8k+i]
    for (int i = tid; i < SUBN * 1024; i += nt) {
        int s = i >> 10;
        int k = (i >> 8) & 3;
        int b = i & 255;
        float v = 0.0f;
        for (int j = 0; j < 8; j++)
            if (b & (1 << j)) v += g_histk[s * T_NO + 8 * k + j];
        g_lut[i] = v;
    }
}

// ---------------- K1: one-hot scatter-sum ----------------
__global__ void agg_kernel(const float* __restrict__ S_e,
                           const float* __restrict__ S_i)
{
    __shared__ float acc_e[SUBN];
    __shared__ float acc_i[SUBN];
    int t   = blockIdx.x;
    int tid = threadIdx.x;
    if (tid < SUBN) { acc_e[tid] = 0.0f; acc_i[tid] = 0.0f; }
    __syncthreads();

    const float* re = S_e + (size_t)t * E_NOC;
    for (int e = tid; e < E_NOC; e += blockDim.x) {
        float v = re[e];
        if (v != 0.0f) atomicAdd(&acc_e[g_idx_e[e]], v);
    }
    const float* ri = S_i + (size_t)t * I_NOC;
    for (int e = tid; e < I_NOC; e += blockDim.x) {
        float v = ri[e];
        if (v != 0.0f) atomicAdd(&acc_i[g_idx_i[e]], v);
    }
    __syncthreads();
    if (tid < SUBN) {
        g_se[t * SUBN + tid] = acc_e[tid];
        g_si[t * SUBN + tid] = acc_i[tid];
    }
}

// ---------------- K2: causal FIR, smem-staged, Theta folded in ----------------
#define CONV_TS 256
#define CONV_THREADS 512
#define CONV_ROWS (CONV_TS + T_NO)
#define CONV_SMEM_FLOATS (4000 + 4000 + CONV_ROWS*SUBN + CONV_ROWS*SUBN)

__global__ void __launch_bounds__(CONV_THREADS, 1)
conv_kernel(const float* __restrict__ Theta)
{
    extern __shared__ float cs[];
    float* ek   = cs;
    float* ik   = ek + 4000;
    float* se_s = ik + 4000;
    float* si_s = se_s + CONV_ROWS * SUBN;

    int tid = threadIdx.x;
    int t0  = blockIdx.x * CONV_TS;

    for (int i = tid; i < SUBN * T_NO; i += CONV_THREADS) {
        ek[i] = g_ek[i];
        ik[i] = g_ik[i];
    }
    for (int i = tid; i < CONV_ROWS * SUBN; i += CONV_THREADS) {
        int r  = i / SUBN;
        int s  = i % SUBN;
        int tg = t0 - T_NO + r;
        float ve = 0.0f, vi = 0.0f;
        if (tg >= 0 && tg < T_DATA) {
            ve = g_se[tg * SUBN + s];
            vi = g_si[tg * SUBN + s];
        }
        se_s[i] = ve;
        si_s[i] = vi;
    }
    __syncthreads();

    for (int wi = tid; wi < CONV_TS * SUBN; wi += CONV_THREADS) {
        int tt = t0 + wi / SUBN;
        int s  = wi % SUBN;
        if (tt >= T_DATA) continue;
        int mmax = min(T_NO, tt);
        int base = ((tt - t0 + T_NO - 1) * SUBN) + s;
        const float* eks = ek + s * T_NO;
        const float* iks = ik + s * T_NO;
        float a0 = 0.0f, a1 = 0.0f;
        for (int m = 0; m < mmax; m++) {
            int ai = base - m * SUBN;
            a0 = fmaf(eks[m], se_s[ai], a0);
            a1 = fmaf(iks[m], si_s[ai], a1);
        }
        g_syn[tt * SUBN + s] = a0 + a1 + Theta[s];
    }
}

// ---------------- K3: blocked recurrence, 14 warps, 2 barriers per 32 steps ----
// Tap split per output t: m=0..31 leader (bitmask+LUT), m=32..63 phase-A mid,
// m=64..199 phase-B far gather (computed one block ahead).
#define RECUR_THREADS 448               // 14 warps; warp 13 = leader (hi-wid priority)
#define RPITCH 513                      // doubled ring pitch (conflict-free)
#define EPITCH 21

#define OFF_ZRING 0                                   // [20][513]
#define OFF_LUT   (OFF_ZRING + SUBN*RPITCH)           // [20][1024]
#define OFF_KHS   (OFF_LUT + SUBN*1024)               // [20][200]
#define OFF_ETOT  (OFF_KHS + SUBN*T_NO)               // [32][21]
#define OFF_HFAR  (OFF_ETOT + BW*EPITCH)              // [32][21]
#define OFF_SYNB  (OFF_HFAR + BW*EPITCH)              // [32][21]
#define RECUR_SMEM_FLOATS (OFF_SYNB + BW*EPITCH)

__global__ void __launch_bounds__(RECUR_THREADS, 1)
recur_kernel(const float* __restrict__ C_den,
             const float* __restrict__ Tau_spk,
             const float* __restrict__ W_spk)
{
    extern __shared__ float sm[];
    float* zring = sm + OFF_ZRING;
    float* lut   = sm + OFF_LUT;
    float* khs   = sm + OFF_KHS;
    float* Etot  = sm + OFF_ETOT;
    float* Hfar  = sm + OFF_HFAR;
    float* synb  = sm + OFF_SYNB;

    int tid  = threadIdx.x;
    int w    = tid >> 5;
    int lane = tid & 31;

    // ---- init smem ----
    for (int i = tid; i < SUBN * RPITCH; i += RECUR_THREADS) zring[i] = 0.0f;
    for (int i = tid; i < SUBN * 1024; i += RECUR_THREADS) lut[i] = g_lut[i];
    for (int i = tid; i < SUBN * T_NO; i += RECUR_THREADS) khs[i] = g_histk[i];
    for (int i = tid; i < BW * EPITCH; i += RECUR_THREADS) {
        int r = i / EPITCH, c = i % EPITCH;
        Hfar[i] = 0.0f;
        Etot[i] = 0.0f;
        synb[i] = (c < SUBN) ? g_syn[r * SUBN + c] : 0.0f;   // block-0 rows
    }

    // ---- leader registers ----
    float rr = 0, cc = 0, U = 0, V = 0, qcur = 0, zfprev = 0;
    unsigned zmask = 0;
    float cd[SUBN];
    #pragma unroll
    for (int j = 0; j < SUBN; j++) cd[j] = 0.0f;
    if (w == 13 && lane < SUBN) {
        rr = expf(-expf(-Tau_spk[lane]));
        cc = expf(W_spk[lane] - Tau_spk[lane]);
        #pragma unroll
        for (int j = 0; j < SUBN; j++) cd[j] = C_den[lane * SUBN + j];
    }
    __syncthreads();

    for (int blk = 0; blk < NBLK; blk++) {
        int T0 = blk * BW;

        // ---------- phase A: mid taps (m=32..63) + Etot fold (warps 0..12) ----------
        if (w < 13) {
            for (int pass = w; pass < SUBN; pass += 13) {
                int s = pass;
                const float*  zp0 = &zring[s * RPITCH + 256 + ((T0 + lane - 1) & 255)];
                const float4* k4p = (const float4*)&khs[s * T_NO];
                float a0 = 0, a1 = 0, a2 = 0, a3 = 0;
                #pragma unroll
                for (int g = 8; g < 16; g++) {            // m = 32..63
                    float4 k4 = k4p[g];
                    a0 = fmaf(k4.x, zp0[-(4 * g + 0)], a0);
                    a1 = fmaf(k4.y, zp0[-(4 * g + 1)], a1);
                    a2 = fmaf(k4.z, zp0[-(4 * g + 2)], a2);
                    a3 = fmaf(k4.w, zp0[-(4 * g + 3)], a3);
                }
                int o = lane * EPITCH + s;
                Etot[o] = ((a0 + a1) + (a2 + a3)) + Hfar[o] + synb[o];
            }
        }
        __syncthreads();

        // ---------- phase B ----------
        if (w == 13) {
            // leader: 32 sequential steps, barrier-free
            for (int p = 0; p < BW; p++) {
                int t = T0 + p;
                float sv = 0.0f;
                if (lane < SUBN) {
                    U = fmaf(rr, U, zfprev);      // u[t] from z[t-1]
                    V = rr * (V + U);             // v[t+1]
                    sv = Etot[p * EPITCH + lane];
                    sv += lut[lane * 1024 +        (zmask & 255u)];
                    sv += lut[lane * 1024 + 256 + ((zmask >> 8)  & 255u)];
                    sv += lut[lane * 1024 + 512 + ((zmask >> 16) & 255u)];
                    sv += lut[lane * 1024 + 768 +  (zmask >> 24)];
                }
                float acc = 0.0f;
                #pragma unroll
                for (int j = 0; j < SUBN; j++) {
                    float qj = __shfl_sync(0xFFFFFFFFu, qcur, j);
                    acc = fmaf(cd[j], qj, acc);
                }
                if (lane < SUBN) {
                    sv += acc;
                    float zf = (sv > 0.0f) ? 1.0f : 0.0f;
                    int slot = t & 255;
                    zring[lane * RPITCH + slot]       = zf;
                    zring[lane * RPITCH + slot + 256] = zf;
                    if (t < T_DATA) g_sv[t * SUBN + lane] = sv;
                    zmask  = (zmask << 1) | (sv > 0.0f ? 1u : 0u);
                    zfprev = zf;
                    qcur   = cc * V;              // q[t+1]
                }
            }
        } else {
            // far gather for NEXT block: m = 64..199 (reads z <= T0-2 only)
            int T0n = T0 + BW;
            for (int pass = w; pass < SUBN; pass += 13) {
                int s = pass;
                const float*  zp0 = &zring[s * RPITCH + 256 + ((T0n + lane - 1) & 255)];
                const float4* k4p = (const float4*)&khs[s * T_NO];
                float a0 = 0, a1 = 0, a2 = 0, a3 = 0;
                #pragma unroll
                for (int g = 16; g < 50; g++) {           // m = 64..199
                    float4 k4 = k4p[g];
                    a0 = fmaf(k4.x, zp0[-(4 * g + 0)], a0);
                    a1 = fmaf(k4.y, zp0[-(4 * g + 1)], a1);
                    a2 = fmaf(k4.z, zp0[-(4 * g + 2)], a2);
                    a3 = fmaf(k4.w, zp0[-(4 * g + 3)], a3);
                }
                Hfar[lane * EPITCH + s] = (a0 + a1) + (a2 + a3);
            }
            if (w == 12 && lane < SUBN) {
                // stage syn rows for next block
                for (int r = 0; r < BW; r++) {
                    int tg = T0 + BW + r;
                    float v = (tg < T_DATA) ? g_syn[tg * SUBN + lane] : 0.0f;
                    synb[r * EPITCH + lane] = v;
                }
            }
        }
        __syncthreads();
    }
}

// ---------------- K4: Z/P from raw pre-activations ----------------
__global__ void zp_kernel(float* __restrict__ Z, float* __restrict__ P)
{
    int idx = blockIdx.x * blockDim.x + threadIdx.x;
    if (idx < T_DATA * SUBN) {
        float sv = g_sv[idx];
        Z[idx] = (sv > 0.0f) ? 1.0f : 0.0f;
        P[idx] = 1.0f / (1.0f + expf(-sv));
    }
}

// ---------------- launch ----------------
extern "C" void kernel_launch(void* const* d_in, const int* in_sizes, int n_in,
                              void* d_out, int out_size)
{
    const float* S_e       = (const float*)d_in[0];
    const float* S_i       = (const float*)d_in[1];
    const float* C_den     = (const float*)d_in[2];
    const float* C_syn_e   = (const float*)d_in[3];
    const float* C_syn_i   = (const float*)d_in[4];
    const float* Tau_syn   = (const float*)d_in[5];
    const float* Delta_syn = (const float*)d_in[6];
    const float* W_syn     = (const float*)d_in[7];
    const float* Tau_spk   = (const float*)d_in[8];
    const float* W_spk     = (const float*)d_in[9];
    const float* W_hist    = (const float*)d_in[10];
    const float* Theta     = (const float*)d_in[11];

    float* out = (float*)d_out;
    float* Z = out;                          // [10000, 20]
    float* P = out + T_DATA * SUBN;          // [10000, 20]
    float* F = out + 2 * T_DATA * SUBN;      // [80, 200]

    prep_kernel<<<1, 256>>>(C_syn_e, C_syn_i, Tau_syn, Delta_syn, W_syn,
                            Tau_spk, W_spk, W_hist, F);
    agg_kernel<<<T_DATA, 256>>>(S_e, S_i);

    cudaFuncSetAttribute(conv_kernel,
                         cudaFuncAttributeMaxDynamicSharedMemorySize,
                         CONV_SMEM_FLOATS * (int)sizeof(float));
    conv_kernel<<<(T_DATA + CONV_TS - 1) / CONV_TS, CONV_THREADS,
                  CONV_SMEM_FLOATS * sizeof(float)>>>(Theta);

    cudaFuncSetAttribute(recur_kernel,
                         cudaFuncAttributeMaxDynamicSharedMemorySize,
                         RECUR_SMEM_FLOATS * (int)sizeof(float));
    recur_kernel<<<1, RECUR_THREADS, RECUR_SMEM_FLOATS * sizeof(float)>>>(
        C_den, Tau_spk, W_spk);

    zp_kernel<<<(T_DATA * SUBN + 255) / 256, 256>>>(Z, P);
}

// round 6
// speedup vs baseline: 1.8979x; 1.0045x over previous
#include <cuda_runtime.h>
#include <math.h>

#define T_NO   200
#define SUBN   20
#define E_NOC  2000
#define I_NOC  500
#define T_DATA 10000
#define COS_NO 17
#define BW     32                       // recurrence block size
#define NBLK   ((T_DATA + BW - 1) / BW) // 313

// ---------------- device scratch (static allocation only) ----------------
__device__ float g_se[T_DATA * SUBN];
__device__ float g_si[T_DATA * SUBN];
__device__ float g_syn[T_DATA * SUBN];    // filtered drive + Theta folded in
__device__ float g_sv[T_DATA * SUBN];     // raw pre-activation
__device__ float g_ek[SUBN * T_NO];
__device__ float g_ik[SUBN * T_NO];
__device__ float g_spkk[SUBN * T_NO];
__device__ float g_histk[SUBN * T_NO];
__device__ float g_lut[SUBN * 1024];      // 4 x 256-entry byte LUTs per subunit (near hist)
__device__ int   g_idx_e[E_NOC];
__device__ int   g_idx_i[I_NOC];

// ---------------- K0: indices + kernels + LUT + filter output ----------------
__global__ void prep_kernel(const float* __restrict__ C_syn_e,
                            const float* __restrict__ C_syn_i,
                            const float* __restrict__ Tau_syn,
                            const float* __restrict__ Delta_syn,
                            const float* __restrict__ W_syn,
                            const float* __restrict__ Tau_spk,
                            const float* __restrict__ W_spk,
                            const float* __restrict__ W_hist,
                            float* __restrict__ filt_out)
{
    int tid = threadIdx.x;
    int nt  = blockDim.x;

    for (int e = tid; e < E_NOC; e += nt) {
        int k = 0;
        for (int s = 0; s < SUBN; s++)
            if (C_syn_e[s * E_NOC + e] > 0.5f) k = s;
        g_idx_e[e] = k;
    }
    for (int e = tid; e < I_NOC; e += nt) {
        int k = 0;
        for (int s = 0; s < SUBN; s++)
            if (C_syn_i[s * I_NOC + e] > 0.5f) k = s;
        g_idx_i[e] = k;
    }

    const float PIF = 3.14159265358979323846f;
    for (int i = tid; i < SUBN * T_NO; i += nt) {
        int s = i / T_NO;
        int m = i % T_NO;
        float mf = (float)m;

        float te  = fmaxf(mf - expf(Delta_syn[s * 2 + 0]), 0.0f);
        float tte = te / expf(Tau_syn[s * 2 + 0]);
        float ek  = tte * expf(-tte) * expf(W_syn[s * 2 + 0]);

        float td  = fmaxf(mf - expf(Delta_syn[s * 2 + 1]), 0.0f);
        float tti = td / expf(Tau_syn[s * 2 + 1]);
        float ik  = -tti * expf(-tti) * expf(W_syn[s * 2 + 1]);

        float tts = mf / expf(Tau_spk[s]);
        float sk  = tts * expf(-tts) * expf(W_spk[s]);

        float raw = 4.0f * logf(mf + 1.0f);
        float hk  = 0.0f;
        for (int c = 0; c < COS_NO; c++) {
            float phi = (PIF * 0.5f) * (float)c;
            if (raw >= phi - PIF && raw <= phi + PIF)
                hk += W_hist[s * COS_NO + c] * (0.5f * cosf(raw - phi) + 0.5f);
        }

        g_ek[i]    = ek;
        g_ik[i]    = ik;
        g_spkk[i]  = sk;
        g_histk[i] = hk;

        filt_out[(0 * SUBN + s) * T_NO + m] = ek;
        filt_out[(1 * SUBN + s) * T_NO + m] = ik;
        filt_out[(2 * SUBN + s) * T_NO + m] = sk;
        filt_out[(3 * SUBN + s) * T_NO + m] = hk;
    }
    __syncthreads();

    // near-hist LUTs: lut[s][k][b] = sum over set bits i of b of histk[s][8k+i]
    for (int i = tid; i < SUBN * 1024; i += nt) {
        int s = i >> 10;
        int k = (i >> 8) & 3;
        int b = i & 255;
        float v = 0.0f;
        for (int j = 0; j < 8; j++)
            if (b & (1 << j)) v += g_histk[s * T_NO + 8 * k + j];
        g_lut[i] = v;
    }
}

// ---------------- K1: one-hot scatter-sum ----------------
__global__ void agg_kernel(const float* __restrict__ S_e,
                           const float* __restrict__ S_i)
{
    __shared__ float acc_e[SUBN];
    __shared__ float acc_i[SUBN];
    int t   = blockIdx.x;
    int tid = threadIdx.x;
    if (tid < SUBN) { acc_e[tid] = 0.0f; acc_i[tid] = 0.0f; }
    __syncthreads();

    const float* re = S_e + (size_t)t * E_NOC;
    for (int e = tid; e < E_NOC; e += blockDim.x) {
        float v = re[e];
        if (v != 0.0f) atomicAdd(&acc_e[g_idx_e[e]], v);
    }
    const float* ri = S_i + (size_t)t * I_NOC;
    for (int e = tid; e < I_NOC; e += blockDim.x) {
        float v = ri[e];
        if (v != 0.0f) atomicAdd(&acc_i[g_idx_i[e]], v);
    }
    __syncthreads();
    if (tid < SUBN) {
        g_se[t * SUBN + tid] = acc_e[tid];
        g_si[t * SUBN + tid] = acc_i[tid];
    }
}

// ---------------- K2: causal FIR, smem-staged, Theta folded in ----------------
#define CONV_TS 256
#define CONV_THREADS 512
#define CONV_ROWS (CONV_TS + T_NO)
#define CONV_SMEM_FLOATS (4000 + 4000 + CONV_ROWS*SUBN + CONV_ROWS*SUBN)

__global__ void __launch_bounds__(CONV_THREADS, 1)
conv_kernel(const float* __restrict__ Theta)
{
    extern __shared__ float cs[];
    float* ek   = cs;
    float* ik   = ek + 4000;
    float* se_s = ik + 4000;
    float* si_s = se_s + CONV_ROWS * SUBN;

    int tid = threadIdx.x;
    int t0  = blockIdx.x * CONV_TS;

    for (int i = tid; i < SUBN * T_NO; i += CONV_THREADS) {
        ek[i] = g_ek[i];
        ik[i] = g_ik[i];
    }
    for (int i = tid; i < CONV_ROWS * SUBN; i += CONV_THREADS) {
        int r  = i / SUBN;
        int s  = i % SUBN;
        int tg = t0 - T_NO + r;
        float ve = 0.0f, vi = 0.0f;
        if (tg >= 0 && tg < T_DATA) {
            ve = g_se[tg * SUBN + s];
            vi = g_si[tg * SUBN + s];
        }
        se_s[i] = ve;
        si_s[i] = vi;
    }
    __syncthreads();

    for (int wi = tid; wi < CONV_TS * SUBN; wi += CONV_THREADS) {
        int tt = t0 + wi / SUBN;
        int s  = wi % SUBN;
        if (tt >= T_DATA) continue;
        int mmax = min(T_NO, tt);
        int base = ((tt - t0 + T_NO - 1) * SUBN) + s;
        const float* eks = ek + s * T_NO;
        const float* iks = ik + s * T_NO;
        float a0 = 0.0f, a1 = 0.0f;
        for (int m = 0; m < mmax; m++) {
            int ai = base - m * SUBN;
            a0 = fmaf(eks[m], se_s[ai], a0);
            a1 = fmaf(iks[m], si_s[ai], a1);
        }
        g_syn[tt * SUBN + s] = a0 + a1 + Theta[s];
    }
}

// ---------------- K3: blocked recurrence, 14 warps, 2 barriers per 32 steps ----
// Tap split per output t: m=0..31 leader (bitmask+LUT), m=32..63 phase-A mid,
// m=64..199 phase-B far gather (computed one block ahead).
// Next-block syn rows are LDG-prefetched by gather warps at the START of
// phase B (registers), stored to smem at the end -> no serial staging tail.
#define RECUR_THREADS 448               // 14 warps; warp 13 = leader (hi-wid priority)
#define RPITCH 513                      // doubled ring pitch (conflict-free)
#define EPITCH 21

#define OFF_ZRING 0                                   // [20][513]
#define OFF_LUT   (OFF_ZRING + SUBN*RPITCH)           // [20][1024]
#define OFF_KHS   (OFF_LUT + SUBN*1024)               // [20][200]
#define OFF_ETOT  (OFF_KHS + SUBN*T_NO)               // [32][21]
#define OFF_HFAR  (OFF_ETOT + BW*EPITCH)              // [32][21]
#define OFF_SYNB  (OFF_HFAR + BW*EPITCH)              // [32][21]
#define RECUR_SMEM_FLOATS (OFF_SYNB + BW*EPITCH)

__global__ void __launch_bounds__(RECUR_THREADS, 1)
recur_kernel(const float* __restrict__ C_den,
             const float* __restrict__ Tau_spk,
             const float* __restrict__ W_spk)
{
    extern __shared__ float sm[];
    float* zring = sm + OFF_ZRING;
    float* lut   = sm + OFF_LUT;
    float* khs   = sm + OFF_KHS;
    float* Etot  = sm + OFF_ETOT;
    float* Hfar  = sm + OFF_HFAR;
    float* synb  = sm + OFF_SYNB;

    int tid  = threadIdx.x;
    int w    = tid >> 5;
    int lane = tid & 31;

    // ---- init smem ----
    for (int i = tid; i < SUBN * RPITCH; i += RECUR_THREADS) zring[i] = 0.0f;
    for (int i = tid; i < SUBN * 1024; i += RECUR_THREADS) lut[i] = g_lut[i];
    for (int i = tid; i < SUBN * T_NO; i += RECUR_THREADS) khs[i] = g_histk[i];
    for (int i = tid; i < BW * EPITCH; i += RECUR_THREADS) {
        int r = i / EPITCH, c = i % EPITCH;
        Hfar[i] = 0.0f;
        Etot[i] = 0.0f;
        synb[i] = (c < SUBN) ? g_syn[r * SUBN + c] : 0.0f;   // block-0 rows
    }

    // ---- leader registers ----
    float rr = 0, cc = 0, U = 0, V = 0, qcur = 0, zfprev = 0;
    unsigned zmask = 0;
    float cd[SUBN];
    #pragma unroll
    for (int j = 0; j < SUBN; j++) cd[j] = 0.0f;
    if (w == 13 && lane < SUBN) {
        rr = expf(-expf(-Tau_spk[lane]));
        cc = expf(W_spk[lane] - Tau_spk[lane]);
        #pragma unroll
        for (int j = 0; j < SUBN; j++) cd[j] = C_den[lane * SUBN + j];
    }

    // gather-warp staging row assignment (rows of the NEXT block's syn)
    int r0 = w, r1 = w + 13, r2 = w + 26;   // r2 valid only for w<6
    __syncthreads();

    for (int blk = 0; blk < NBLK; blk++) {
        int T0 = blk * BW;

        // ---------- phase A: mid taps (m=32..63) + Etot fold (warps 0..12) ----------
        if (w < 13) {
            for (int pass = w; pass < SUBN; pass += 13) {
                int s = pass;
                const float*  zp0 = &zring[s * RPITCH + 256 + ((T0 + lane - 1) & 255)];
                const float4* k4p = (const float4*)&khs[s * T_NO];
                float a0 = 0, a1 = 0, a2 = 0, a3 = 0;
                #pragma unroll
                for (int g = 8; g < 16; g++) {            // m = 32..63
                    float4 k4 = k4p[g];
                    a0 = fmaf(k4.x, zp0[-(4 * g + 0)], a0);
                    a1 = fmaf(k4.y, zp0[-(4 * g + 1)], a1);
                    a2 = fmaf(k4.z, zp0[-(4 * g + 2)], a2);
                    a3 = fmaf(k4.w, zp0[-(4 * g + 3)], a3);
                }
                int o = lane * EPITCH + s;
                Etot[o] = ((a0 + a1) + (a2 + a3)) + Hfar[o] + synb[o];
            }
        }
        __syncthreads();

        // ---------- phase B ----------
        if (w == 13) {
            // leader: 32 sequential steps, barrier-free
            for (int p = 0; p < BW; p++) {
                int t = T0 + p;
                float sv = 0.0f;
                if (lane < SUBN) {
                    U = fmaf(rr, U, zfprev);      // u[t] from z[t-1]
                    V = rr * (V + U);             // v[t+1]
                    sv = Etot[p * EPITCH + lane];
                    sv += lut[lane * 1024 +        (zmask & 255u)];
                    sv += lut[lane * 1024 + 256 + ((zmask >> 8)  & 255u)];
                    sv += lut[lane * 1024 + 512 + ((zmask >> 16) & 255u)];
                    sv += lut[lane * 1024 + 768 +  (zmask >> 24)];
                }
                // C_den @ q via 4 independent shfl+FMA chains
                float a0 = 0, a1 = 0, a2 = 0, a3 = 0;
                #pragma unroll
                for (int j = 0; j < 5; j++) {
                    float q0 = __shfl_sync(0xFFFFFFFFu, qcur, j);
                    float q1 = __shfl_sync(0xFFFFFFFFu, qcur, j + 5);
                    float q2 = __shfl_sync(0xFFFFFFFFu, qcur, j + 10);
                    float q3 = __shfl_sync(0xFFFFFFFFu, qcur, j + 15);
                    a0 = fmaf(cd[j],      q0, a0);
                    a1 = fmaf(cd[j + 5],  q1, a1);
                    a2 = fmaf(cd[j + 10], q2, a2);
                    a3 = fmaf(cd[j + 15], q3, a3);
                }
                if (lane < SUBN) {
                    sv += (a0 + a1) + (a2 + a3);
                    float zf = (sv > 0.0f) ? 1.0f : 0.0f;
                    int slot = t & 255;
                    zring[lane * RPITCH + slot]       = zf;
                    zring[lane * RPITCH + slot + 256] = zf;
                    if (t < T_DATA) g_sv[t * SUBN + lane] = sv;
                    zmask  = (zmask << 1) | (sv > 0.0f ? 1u : 0u);
                    zfprev = zf;
                    qcur   = cc * V;              // q[t+1]
                }
            }
        } else {
            // prefetch next-block syn rows into registers (MLP-hidden)
            float pf0 = 0.0f, pf1 = 0.0f, pf2 = 0.0f;
            if (lane < SUBN) {
                int tg0 = T0 + BW + r0;
                int tg1 = T0 + BW + r1;
                pf0 = (tg0 < T_DATA) ? g_syn[tg0 * SUBN + lane] : 0.0f;
                pf1 = (tg1 < T_DATA) ? g_syn[tg1 * SUBN + lane] : 0.0f;
                if (r2 < BW) {
                    int tg2 = T0 + BW + r2;
                    pf2 = (tg2 < T_DATA) ? g_syn[tg2 * SUBN + lane] : 0.0f;
                }
            }

            // far gather for NEXT block: m = 64..199 (reads z <= T0-2 only)
            int T0n = T0 + BW;
            for (int pass = w; pass < SUBN; pass += 13) {
                int s = pass;
                const float*  zp0 = &zring[s * RPITCH + 256 + ((T0n + lane - 1) & 255)];
                const float4* k4p = (const float4*)&khs[s * T_NO];
                float a0 = 0, a1 = 0, a2 = 0, a3 = 0;
                #pragma unroll
                for (int g = 16; g < 50; g++) {           // m = 64..199
                    float4 k4 = k4p[g];
                    a0 = fmaf(k4.x, zp0[-(4 * g + 0)], a0);
                    a1 = fmaf(k4.y, zp0[-(4 * g + 1)], a1);
                    a2 = fmaf(k4.z, zp0[-(4 * g + 2)], a2);
                    a3 = fmaf(k4.w, zp0[-(4 * g + 3)], a3);
                }
                Hfar[lane * EPITCH + s] = (a0 + a1) + (a2 + a3);
            }

            // store staged rows (phase A of this block already consumed synb)
            if (lane < SUBN) {
                synb[r0 * EPITCH + lane] = pf0;
                synb[r1 * EPITCH + lane] = pf1;
                if (r2 < BW) synb[r2 * EPITCH + lane] = pf2;
            }
        }
        __syncthreads();
    }
}

// ---------------- K4: Z/P from raw pre-activations ----------------
__global__ void zp_kernel(float* __restrict__ Z, float* __restrict__ P)
{
    int idx = blockIdx.x * blockDim.x + threadIdx.x;
    if (idx < T_DATA * SUBN) {
        float sv = g_sv[idx];
        Z[idx] = (sv > 0.0f) ? 1.0f : 0.0f;
        P[idx] = 1.0f / (1.0f + expf(-sv));
    }
}

// ---------------- launch ----------------
extern "C" void kernel_launch(void* const* d_in, const int* in_sizes, int n_in,
                              void* d_out, int out_size)
{
    const float* S_e       = (const float*)d_in[0];
    const float* S_i       = (const float*)d_in[1];
    const float* C_den     = (const float*)d_in[2];
    const float* C_syn_e   = (const float*)d_in[3];
    const float* C_syn_i   = (const float*)d_in[4];
    const float* Tau_syn   = (const float*)d_in[5];
    const float* Delta_syn = (const float*)d_in[6];
    const float* W_syn     = (const float*)d_in[7];
    const float* Tau_spk   = (const float*)d_in[8];
    const float* W_spk     = (const float*)d_in[9];
    const float* W_hist    = (const float*)d_in[10];
    const float* Theta     = (const float*)d_in[11];

    float* out = (float*)d_out;
    float* Z = out;                          // [10000, 20]
    float* P = out + T_DATA * SUBN;          // [10000, 20]
    float* F = out + 2 * T_DATA * SUBN;      // [80, 200]

    prep_kernel<<<1, 256>>>(C_syn_e, C_syn_i, Tau_syn, Delta_syn, W_syn,
                            Tau_spk, W_spk, W_hist, F);
    agg_kernel<<<T_DATA, 256>>>(S_e, S_i);

    cudaFuncSetAttribute(conv_kernel,
                         cudaFuncAttributeMaxDynamicSharedMemorySize,
                         CONV_SMEM_FLOATS * (int)sizeof(float));
    conv_kernel<<<(T_DATA + CONV_TS - 1) / CONV_TS, CONV_THREADS,
                  CONV_SMEM_FLOATS * sizeof(float)>>>(Theta);

    cudaFuncSetAttribute(recur_kernel,
                         cudaFuncAttributeMaxDynamicSharedMemorySize,
                         RECUR_SMEM_FLOATS * (int)sizeof(float));
    recur_kernel<<<1, RECUR_THREADS, RECUR_SMEM_FLOATS * sizeof(float)>>>(
        C_den, Tau_spk, W_spk);

    zp_kernel<<<(T_DATA * SUBN + 255) / 256, 256>>>(Z, P);
}